// round 7
// baseline (speedup 1.0000x reference)
#include <cuda_runtime.h>
#include <cuda_bf16.h>
#include <math.h>
#include <stdint.h>

#define DIM    512
#define NNEUR  4096
#define BT     8192   // B*T

// quantization scales for GEMM1 (x ~ N(0,1), pos ~ 0.1*N(0,1); 5.5-sigma clamp)
#define SX 22.0f
#define SP 230.0f

// ---------------- scratch (device globals; allocation-free) ----------------
__device__ float                       g_p2[NNEUR];
__device__ float                       g_x2[BT];
__device__ float                       g_cvec[DIM];
__device__ __align__(16) int8_t        g_xq[BT * DIM];                 // 4 MB
__device__ __align__(16) int8_t        g_pq[NNEUR * DIM];              // 2 MB
__device__ __align__(16) __nv_bfloat16 g_pb[NNEUR * DIM];              // 4 MB
__device__ __align__(16) __nv_bfloat16 g_wvb[DIM * DIM];               // 0.5 MB
__device__ __align__(16) __nv_bfloat16 g_wob[DIM * DIM];               // 0.5 MB
__device__ __align__(16) __nv_bfloat16 g_valb[NNEUR * DIM];            // 4 MB  values
__device__ __align__(16) __nv_bfloat16 g_w2b[DIM * NNEUR];             // 4 MB  W2^T
__device__ __align__(16) __nv_bfloat16 g_attn[(size_t)BT * NNEUR];     // 64 MB

// ---------------- warp-mma helpers (base ISA: sm_80+, no 'a' suffix) -------
__device__ __forceinline__ uint32_t smem_to_u32(const void* p) {
    uint32_t a;
    asm("{ .reg .u64 t; cvta.to.shared.u64 t, %1; cvt.u32.u64 %0, t; }" : "=r"(a) : "l"(p));
    return a;
}
__device__ __forceinline__ void ldsm4(uint32_t& r0, uint32_t& r1, uint32_t& r2,
                                      uint32_t& r3, uint32_t addr) {
    asm volatile("ldmatrix.sync.aligned.m8n8.x4.shared.b16 {%0,%1,%2,%3}, [%4];"
                 : "=r"(r0), "=r"(r1), "=r"(r2), "=r"(r3) : "r"(addr));
}
__device__ __forceinline__ void mma16816(float* c, const uint32_t* a,
                                         uint32_t b0, uint32_t b1) {
    asm volatile(
        "mma.sync.aligned.m16n8k16.row.col.f32.bf16.bf16.f32 "
        "{%0,%1,%2,%3}, {%4,%5,%6,%7}, {%8,%9}, {%0,%1,%2,%3};"
        : "+f"(c[0]), "+f"(c[1]), "+f"(c[2]), "+f"(c[3])
        : "r"(a[0]), "r"(a[1]), "r"(a[2]), "r"(a[3]), "r"(b0), "r"(b1));
}
__device__ __forceinline__ void mma16832s8(int* c, const uint32_t* a,
                                           uint32_t b0, uint32_t b1) {
    asm volatile(
        "mma.sync.aligned.m16n8k32.row.col.s32.s8.s8.s32 "
        "{%0,%1,%2,%3}, {%4,%5,%6,%7}, {%8,%9}, {%0,%1,%2,%3};"
        : "+r"(c[0]), "+r"(c[1]), "+r"(c[2]), "+r"(c[3])
        : "r"(a[0]), "r"(a[1]), "r"(a[2]), "r"(a[3]), "r"(b0), "r"(b1));
}
__device__ __forceinline__ void cp16(uint32_t dst, const void* src) {
    asm volatile("cp.async.cg.shared.global [%0], [%1], 16;" :: "r"(dst), "l"(src));
}
#define CP_COMMIT() asm volatile("cp.async.commit_group;" ::: "memory")
#define CP_WAIT(n)  asm volatile("cp.async.wait_group %0;" :: "n"(n) : "memory")

// swizzled smem offset for 64B rows (4 x 16B chunks), conflict-free ldmatrix
__device__ __forceinline__ uint32_t swz_off(int row, int chunk) {
    return (uint32_t)(row * 64 + ((chunk ^ ((row >> 1) & 3)) << 4));
}

// ---------------------------------------------------------------------------
// bf16 mma_gemm: C[M,N] = A[M,K] @ B[N,K]^T, fp32 acc.
// BM=128, BN=128, BK=32, 256 threads = 8 warps (2 m x 4 n), warp tile 64x32.
// 3-stage cp.async pipeline (stage = 16 KB).  Requires niter >= 2.
// EPI 2: plain bf16 out.  EPI 3: +bias[n] -> fp32 out.
// ---------------------------------------------------------------------------
static constexpr int MG_STAGES = 3;
static constexpr int MG_SMEM   = MG_STAGES * 16384;   // 48 KB dynamic

template <int EPI>
__global__ __launch_bounds__(256) void mma_gemm(
    const __nv_bfloat16* __restrict__ A, const __nv_bfloat16* __restrict__ B,
    void* __restrict__ Cv, int ldA, int ldB, int ldC, int niter,
    const float* __restrict__ bias)
{
    extern __shared__ __align__(128) char dsm[];
    __shared__ float scs[128];

    const int tid  = threadIdx.x;
    const int lane = tid & 31, wid = tid >> 5;
    const int warp_m = wid >> 2, warp_n = wid & 3;
    const int bm = blockIdx.y * 128, bn = blockIdx.x * 128;

    if (EPI == 3 && tid < 128) scs[tid] = bias[bn + tid];

    const int lrow = tid >> 2;
    const int lchk = tid & 3;
    const uint32_t su = smem_to_u32(dsm);

    auto issue = [&](int it) {
        const int slot = it % MG_STAGES;
        const int k0 = it * 32;
        const uint32_t ab = su + slot * 16384;
        const uint32_t bb = ab + 8192;
#pragma unroll
        for (int h = 0; h < 2; h++) {
            const int r = lrow + h * 64;
            cp16(ab + swz_off(r, lchk), A + (size_t)(bm + r) * ldA + k0 + lchk * 8);
            cp16(bb + swz_off(r, lchk), B + (size_t)(bn + r) * ldB + k0 + lchk * 8);
        }
        CP_COMMIT();
    };

    issue(0);
    issue(1);

    float acc[4][4][4] = {};
    const int rin = lane & 7, matid = lane >> 3;

    for (int it = 0; it < niter; it++) {
        if (it == niter - 1) CP_WAIT(0); else CP_WAIT(1);
        __syncthreads();
        if (it + MG_STAGES - 1 < niter) issue(it + MG_STAGES - 1);

        const uint32_t a_s = su + (it % MG_STAGES) * 16384;
        const uint32_t b_s = a_s + 8192;
#pragma unroll
        for (int s = 0; s < 2; s++) {
            uint32_t af[4][4], bf[2][4];
#pragma unroll
            for (int mb = 0; mb < 4; mb++) {
                const int row = warp_m * 64 + mb * 16 + (matid & 1) * 8 + rin;
                const int chk = s * 2 + (matid >> 1);
                ldsm4(af[mb][0], af[mb][1], af[mb][2], af[mb][3], a_s + swz_off(row, chk));
            }
#pragma unroll
            for (int nb2 = 0; nb2 < 2; nb2++) {
                const int row = warp_n * 32 + nb2 * 16 + (matid >> 1) * 8 + rin;
                const int chk = s * 2 + (matid & 1);
                ldsm4(bf[nb2][0], bf[nb2][1], bf[nb2][2], bf[nb2][3], b_s + swz_off(row, chk));
            }
#pragma unroll
            for (int mb = 0; mb < 4; mb++)
#pragma unroll
                for (int nb = 0; nb < 4; nb++)
                    mma16816(acc[mb][nb], af[mb],
                             bf[nb >> 1][(nb & 1) * 2], bf[nb >> 1][(nb & 1) * 2 + 1]);
        }
    }

    const int g = lane >> 2, tig = lane & 3;
#pragma unroll
    for (int mb = 0; mb < 4; mb++) {
        const int r0 = warp_m * 64 + mb * 16 + g;
#pragma unroll
        for (int nb = 0; nb < 4; nb++) {
            const int cl = warp_n * 32 + nb * 8 + 2 * tig;
            const float* c = acc[mb][nb];
            if (EPI == 2) {
                __nv_bfloat16* Cb = reinterpret_cast<__nv_bfloat16*>(Cv);
                *reinterpret_cast<__nv_bfloat162*>(Cb + (size_t)(bm + r0) * ldC + bn + cl) =
                    __floats2bfloat162_rn(c[0], c[1]);
                *reinterpret_cast<__nv_bfloat162*>(Cb + (size_t)(bm + r0 + 8) * ldC + bn + cl) =
                    __floats2bfloat162_rn(c[2], c[3]);
            } else {
                const float b0 = scs[cl], b1 = scs[cl + 1];
                float* Cf = reinterpret_cast<float*>(Cv);
                *reinterpret_cast<float2*>(Cf + (size_t)(bm + r0) * ldC + bn + cl) =
                    make_float2(c[0] + b0, c[1] + b1);
                *reinterpret_cast<float2*>(Cf + (size_t)(bm + r0 + 8) * ldC + bn + cl) =
                    make_float2(c[2] + b0, c[3] + b1);
            }
        }
    }
}

// ---------------------------------------------------------------------------
// gemm1_s8: interactions = f(x @ pos^T), int8 MMA (m16n8k32, s32 acc).
// A = x_q [BT][512]B, B = pos_q [NNEUR][512]B. BK=64 bytes, 8 K-iters.
// s8-k32 fragments byte-alias bf16-k16 fragments -> identical ldmatrix code.
// Fused interaction epilogue -> bf16 attn logits.
// ---------------------------------------------------------------------------
__global__ __launch_bounds__(256) void gemm1_s8(
    const int8_t* __restrict__ A, const int8_t* __restrict__ B,
    __nv_bfloat16* __restrict__ Cb,
    const float* __restrict__ x2, const float* __restrict__ p2,
    const float* __restrict__ scale)
{
    extern __shared__ __align__(128) char dsm[];
    __shared__ float p2s[128], scs[128];

    const int tid  = threadIdx.x;
    const int lane = tid & 31, wid = tid >> 5;
    const int warp_m = wid >> 2, warp_n = wid & 3;
    const int bm = blockIdx.y * 128, bn = blockIdx.x * 128;
    constexpr int NITER = DIM / 64;        // 8

    if (tid < 128) {
        p2s[tid] = p2[bn + tid];
        scs[tid] = scale[bn + tid];
    }

    const int lrow = tid >> 2;
    const int lchk = tid & 3;
    const uint32_t su = smem_to_u32(dsm);

    auto issue = [&](int it) {
        const int slot = it % MG_STAGES;
        const int k0 = it * 64;            // bytes
        const uint32_t ab = su + slot * 16384;
        const uint32_t bb = ab + 8192;
#pragma unroll
        for (int h = 0; h < 2; h++) {
            const int r = lrow + h * 64;
            cp16(ab + swz_off(r, lchk), A + (size_t)(bm + r) * DIM + k0 + lchk * 16);
            cp16(bb + swz_off(r, lchk), B + (size_t)(bn + r) * DIM + k0 + lchk * 16);
        }
        CP_COMMIT();
    };

    issue(0);
    issue(1);

    int acc[4][4][4] = {};
    const int rin = lane & 7, matid = lane >> 3;

    for (int it = 0; it < NITER; it++) {
        if (it == NITER - 1) CP_WAIT(0); else CP_WAIT(1);
        __syncthreads();
        if (it + MG_STAGES - 1 < NITER) issue(it + MG_STAGES - 1);

        const uint32_t a_s = su + (it % MG_STAGES) * 16384;
        const uint32_t b_s = a_s + 8192;
#pragma unroll
        for (int s = 0; s < 2; s++) {      // two k32 steps per 64B chunk
            uint32_t af[4][4], bf[2][4];
#pragma unroll
            for (int mb = 0; mb < 4; mb++) {
                const int row = warp_m * 64 + mb * 16 + (matid & 1) * 8 + rin;
                const int chk = s * 2 + (matid >> 1);
                ldsm4(af[mb][0], af[mb][1], af[mb][2], af[mb][3], a_s + swz_off(row, chk));
            }
#pragma unroll
            for (int nb2 = 0; nb2 < 2; nb2++) {
                const int row = warp_n * 32 + nb2 * 16 + (matid >> 1) * 8 + rin;
                const int chk = s * 2 + (matid & 1);
                ldsm4(bf[nb2][0], bf[nb2][1], bf[nb2][2], bf[nb2][3], b_s + swz_off(row, chk));
            }
#pragma unroll
            for (int mb = 0; mb < 4; mb++)
#pragma unroll
                for (int nb = 0; nb < 4; nb++)
                    mma16832s8(acc[mb][nb], af[mb],
                               bf[nb >> 1][(nb & 1) * 2], bf[nb >> 1][(nb & 1) * 2 + 1]);
        }
    }

    // ---- interaction epilogue ----
    constexpr float INV = 1.0f / (SX * SP);
    const int g = lane >> 2, tig = lane & 3;
#pragma unroll
    for (int mb = 0; mb < 4; mb++) {
        const int r0 = warp_m * 64 + mb * 16 + g;
        const float xa = x2[bm + r0], xb = x2[bm + r0 + 8];
#pragma unroll
        for (int nb = 0; nb < 4; nb++) {
            const int cl = warp_n * 32 + nb * 8 + 2 * tig;
            const int* c = acc[mb][nb];
            const float p0 = p2s[cl], p1 = p2s[cl + 1];
            const float s0 = scs[cl], s1 = scs[cl + 1];
            const float c0 = (float)c[0] * INV, c1 = (float)c[1] * INV;
            const float c2 = (float)c[2] * INV, c3 = (float)c[3] * INV;
            float q0 = fmaxf(xa - 2.f * c0 + p0, 0.f);
            float q1 = fmaxf(xa - 2.f * c1 + p1, 0.f);
            float q2 = fmaxf(xb - 2.f * c2 + p0, 0.f);
            float q3 = fmaxf(xb - 2.f * c3 + p1, 0.f);
            *reinterpret_cast<__nv_bfloat162*>(Cb + (size_t)(bm + r0) * NNEUR + bn + cl) =
                __floats2bfloat162_rn(s0 / (sqrtf(q0) + 0.1f), s1 / (sqrtf(q1) + 0.1f));
            *reinterpret_cast<__nv_bfloat162*>(Cb + (size_t)(bm + r0 + 8) * NNEUR + bn + cl) =
                __floats2bfloat162_rn(s0 / (sqrtf(q2) + 0.1f), s1 / (sqrtf(q3) + 0.1f));
        }
    }
}

// ---------------------------------------------------------------------------
// conversions
// ---------------------------------------------------------------------------
__device__ __forceinline__ int8_t q8(float v, float s) {
    return (int8_t)fminf(fmaxf(rintf(v * s), -127.f), 127.f);
}

// x: fp32 -> s8 + row sum-of-squares (1 block / row, 128 thr)
__global__ void conv_x(const float* __restrict__ A, int8_t* __restrict__ Aq,
                       float* __restrict__ out) {
    const int row = blockIdx.x;
    const int tid = threadIdx.x;
    const float4 v = reinterpret_cast<const float4*>(A + (size_t)row * DIM)[tid];
    float s = v.x * v.x + v.y * v.y + v.z * v.z + v.w * v.w;
    char4 q = { q8(v.x, SX), q8(v.y, SX), q8(v.z, SX), q8(v.w, SX) };
    reinterpret_cast<char4*>(Aq + (size_t)row * DIM)[tid] = q;
#pragma unroll
    for (int off = 16; off > 0; off >>= 1) s += __shfl_down_sync(0xffffffffu, s, off);
    __shared__ float ws[4];
    if ((tid & 31) == 0) ws[tid >> 5] = s;
    __syncthreads();
    if (tid == 0) out[row] = ws[0] + ws[1] + ws[2] + ws[3];
}

// pos: fp32 -> s8 + bf16 + row sum-of-squares
__global__ void conv_pos(const float* __restrict__ A, int8_t* __restrict__ Aq,
                         __nv_bfloat16* __restrict__ Ab, float* __restrict__ out) {
    const int row = blockIdx.x;
    const int tid = threadIdx.x;
    const float4 v = reinterpret_cast<const float4*>(A + (size_t)row * DIM)[tid];
    float s = v.x * v.x + v.y * v.y + v.z * v.z + v.w * v.w;
    char4 q = { q8(v.x, SP), q8(v.y, SP), q8(v.z, SP), q8(v.w, SP) };
    reinterpret_cast<char4*>(Aq + (size_t)row * DIM)[tid] = q;
    union { uint2 u; __nv_bfloat162 h[2]; } w;
    w.h[0] = __floats2bfloat162_rn(v.x, v.y);
    w.h[1] = __floats2bfloat162_rn(v.z, v.w);
    reinterpret_cast<uint2*>(Ab + (size_t)row * DIM)[tid] = w.u;
#pragma unroll
    for (int off = 16; off > 0; off >>= 1) s += __shfl_down_sync(0xffffffffu, s, off);
    __shared__ float ws[4];
    if ((tid & 31) == 0) ws[tid >> 5] = s;
    __syncthreads();
    if (tid == 0) out[row] = ws[0] + ws[1] + ws[2] + ws[3];
}

// plain fp32 -> bf16 convert (1 block / row of DIM, 128 thr)
__global__ void conv_only(const float* __restrict__ A, __nv_bfloat16* __restrict__ Ab) {
    const int row = blockIdx.x;
    const int tid = threadIdx.x;
    const float4 v = reinterpret_cast<const float4*>(A + (size_t)row * DIM)[tid];
    union { uint2 u; __nv_bfloat162 h[2]; } w;
    w.h[0] = __floats2bfloat162_rn(v.x, v.y);
    w.h[1] = __floats2bfloat162_rn(v.z, v.w);
    reinterpret_cast<uint2*>(Ab + (size_t)row * DIM)[tid] = w.u;
}

// cvec[d] = b_o[d] + dot(w_o[d,:], b_v)
__global__ void cvec_kernel(const float* __restrict__ w_o, const float* __restrict__ b_v,
                            const float* __restrict__ b_o, float* __restrict__ cvec) {
    const int d = blockIdx.x;
    const int tid = threadIdx.x;
    float s = 0.f;
#pragma unroll
    for (int i = tid; i < DIM; i += 128) s += w_o[(size_t)d * DIM + i] * b_v[i];
#pragma unroll
    for (int off = 16; off > 0; off >>= 1) s += __shfl_down_sync(0xffffffffu, s, off);
    __shared__ float ws[4];
    if ((tid & 31) == 0) ws[tid >> 5] = s;
    __syncthreads();
    if (tid == 0) cvec[d] = b_o[d] + ws[0] + ws[1] + ws[2] + ws[3];
}

// ---------------------------------------------------------------------------
// row softmax over 4096 bf16, in place (fp32 math), 1 block / row, 256 thr
// ---------------------------------------------------------------------------
__global__ __launch_bounds__(256) void softmax_bf16(__nv_bfloat16* __restrict__ data) {
    const int row = blockIdx.x;
    const int tid = threadIdx.x;
    uint4* p = reinterpret_cast<uint4*>(data + (size_t)row * NNEUR);
    uint4 a = p[tid], b = p[tid + 256];
    float f[16];
    const __nv_bfloat162* ha = reinterpret_cast<const __nv_bfloat162*>(&a);
    const __nv_bfloat162* hb = reinterpret_cast<const __nv_bfloat162*>(&b);
#pragma unroll
    for (int i = 0; i < 4; i++) {
        float2 u = __bfloat1622float2(ha[i]);
        f[2 * i] = u.x; f[2 * i + 1] = u.y;
        float2 w = __bfloat1622float2(hb[i]);
        f[8 + 2 * i] = w.x; f[8 + 2 * i + 1] = w.y;
    }
    float mx = f[0];
#pragma unroll
    for (int i = 1; i < 16; i++) mx = fmaxf(mx, f[i]);
    __shared__ float red[8];
#pragma unroll
    for (int off = 16; off > 0; off >>= 1)
        mx = fmaxf(mx, __shfl_xor_sync(0xffffffffu, mx, off));
    if ((tid & 31) == 0) red[tid >> 5] = mx;
    __syncthreads();
    mx = red[0];
#pragma unroll
    for (int w = 1; w < 8; w++) mx = fmaxf(mx, red[w]);

    float s = 0.f;
#pragma unroll
    for (int i = 0; i < 16; i++) { f[i] = __expf(f[i] - mx); s += f[i]; }
#pragma unroll
    for (int off = 16; off > 0; off >>= 1) s += __shfl_xor_sync(0xffffffffu, s, off);
    __syncthreads();
    if ((tid & 31) == 0) red[tid >> 5] = s;
    __syncthreads();
    s = red[0] + red[1] + red[2] + red[3] + red[4] + red[5] + red[6] + red[7];
    const float inv = 1.0f / s;

    __nv_bfloat162* oa = reinterpret_cast<__nv_bfloat162*>(&a);
    __nv_bfloat162* ob = reinterpret_cast<__nv_bfloat162*>(&b);
#pragma unroll
    for (int i = 0; i < 4; i++) {
        oa[i] = __floats2bfloat162_rn(f[2 * i] * inv, f[2 * i + 1] * inv);
        ob[i] = __floats2bfloat162_rn(f[8 + 2 * i] * inv, f[8 + 2 * i + 1] * inv);
    }
    p[tid] = a;
    p[tid + 256] = b;
}

// ---------------------------------------------------------------------------
extern "C" void kernel_launch(void* const* d_in, const int* in_sizes, int n_in,
                              void* d_out, int out_size)
{
    const float* x     = (const float*)d_in[0];
    const float* pos   = (const float*)d_in[1];
    const float* scale = (const float*)d_in[2];
    const float* w_v   = (const float*)d_in[3];
    const float* b_v   = (const float*)d_in[4];
    const float* w_o   = (const float*)d_in[5];
    const float* b_o   = (const float*)d_in[6];
    float* out = (float*)d_out;

    static float* pp2 = nullptr;
    static float *px2, *pcv;
    static int8_t *pxq, *ppq;
    static __nv_bfloat16 *ppb, *pwvb, *pwob, *pvalb, *pw2b, *pattn;
    if (pp2 == nullptr) {
        cudaGetSymbolAddress((void**)&pp2,   g_p2);
        cudaGetSymbolAddress((void**)&px2,   g_x2);
        cudaGetSymbolAddress((void**)&pcv,   g_cvec);
        cudaGetSymbolAddress((void**)&pxq,   g_xq);
        cudaGetSymbolAddress((void**)&ppq,   g_pq);
        cudaGetSymbolAddress((void**)&ppb,   g_pb);
        cudaGetSymbolAddress((void**)&pwvb,  g_wvb);
        cudaGetSymbolAddress((void**)&pwob,  g_wob);
        cudaGetSymbolAddress((void**)&pvalb, g_valb);
        cudaGetSymbolAddress((void**)&pw2b,  g_w2b);
        cudaGetSymbolAddress((void**)&pattn, g_attn);
        cudaFuncSetAttribute(mma_gemm<2>, cudaFuncAttributeMaxDynamicSharedMemorySize, MG_SMEM);
        cudaFuncSetAttribute(mma_gemm<3>, cudaFuncAttributeMaxDynamicSharedMemorySize, MG_SMEM);
        cudaFuncSetAttribute(gemm1_s8,    cudaFuncAttributeMaxDynamicSharedMemorySize, MG_SMEM);
    }

    // converts + norms
    conv_x  <<<BT,    128>>>(x,   pxq, px2);
    conv_pos<<<NNEUR, 128>>>(pos, ppq, ppb, pp2);
    conv_only<<<DIM,  128>>>(w_v, pwvb);
    conv_only<<<DIM,  128>>>(w_o, pwob);
    cvec_kernel<<<DIM, 128>>>(w_o, b_v, b_o, pcv);

    // values = pos @ w_v^T           (4096 x 512, K=512, bf16 out)
    mma_gemm<2><<<dim3(DIM / 128, NNEUR / 128), 256, MG_SMEM>>>(
        ppb, pwvb, pvalb, DIM, DIM, DIM, DIM / 32, nullptr);

    // W2^T = w_o @ values^T          (512 x 4096, K=512, bf16 out)
    mma_gemm<2><<<dim3(NNEUR / 128, DIM / 128), 256, MG_SMEM>>>(
        pwob, pvalb, pw2b, DIM, DIM, NNEUR, DIM / 32, nullptr);

    // interactions = f(x @ pos^T)    (8192 x 4096, K=512, int8 MMA -> bf16)
    gemm1_s8<<<dim3(NNEUR / 128, BT / 128), 256, MG_SMEM>>>(
        pxq, ppq, pattn, px2, pp2, scale);

    // softmax over neurons (bf16 in/out, fp32 math)
    softmax_bf16<<<BT, 256>>>(pattn);

    // out = attn @ W2 + cvec         (8192 x 512, K=4096, fp32 out, bias epi)
    mma_gemm<3><<<dim3(DIM / 128, BT / 128), 256, MG_SMEM>>>(
        pattn, pw2b, out, NNEUR, NNEUR, DIM, NNEUR / 32, pcv);
}

// round 8
// speedup vs baseline: 1.4492x; 1.4492x over previous
#include <cuda_runtime.h>
#include <cuda_bf16.h>
#include <math.h>
#include <stdint.h>

#define DIM    512
#define NNEUR  4096
#define BT     8192   // B*T
#define NBLK1  (NNEUR / 128)   // 32 column-blocks in GEMM1

// ---------------- scratch (device globals; allocation-free) ----------------
__device__ float                       g_p2[NNEUR];
__device__ float                       g_x2[BT];
__device__ float                       g_cvec[DIM];
__device__ float                       g_S[BT];
__device__ __align__(16) float         g_psum[(size_t)BT * NBLK1];     // 1 MB
__device__ __align__(16) __nv_bfloat16 g_xb[BT * DIM];                 // 8 MB
__device__ __align__(16) __nv_bfloat16 g_pb[NNEUR * DIM];              // 4 MB
__device__ __align__(16) __nv_bfloat16 g_wvb[DIM * DIM];               // 0.5 MB
__device__ __align__(16) __nv_bfloat16 g_wob[DIM * DIM];               // 0.5 MB
__device__ __align__(16) __nv_bfloat16 g_valb[NNEUR * DIM];            // 4 MB  values
__device__ __align__(16) __nv_bfloat16 g_w2b[DIM * NNEUR];             // 4 MB  W2^T
__device__ __align__(16) __nv_bfloat16 g_attn[(size_t)BT * NNEUR];     // 64 MB (e = exp)

// ---------------- warp-mma helpers (base ISA: sm_80+, no 'a' suffix) -------
__device__ __forceinline__ uint32_t smem_to_u32(const void* p) {
    uint32_t a;
    asm("{ .reg .u64 t; cvta.to.shared.u64 t, %1; cvt.u32.u64 %0, t; }" : "=r"(a) : "l"(p));
    return a;
}
__device__ __forceinline__ void ldsm4(uint32_t& r0, uint32_t& r1, uint32_t& r2,
                                      uint32_t& r3, uint32_t addr) {
    asm volatile("ldmatrix.sync.aligned.m8n8.x4.shared.b16 {%0,%1,%2,%3}, [%4];"
                 : "=r"(r0), "=r"(r1), "=r"(r2), "=r"(r3) : "r"(addr));
}
__device__ __forceinline__ void mma16816(float* c, const uint32_t* a,
                                         uint32_t b0, uint32_t b1) {
    asm volatile(
        "mma.sync.aligned.m16n8k16.row.col.f32.bf16.bf16.f32 "
        "{%0,%1,%2,%3}, {%4,%5,%6,%7}, {%8,%9}, {%0,%1,%2,%3};"
        : "+f"(c[0]), "+f"(c[1]), "+f"(c[2]), "+f"(c[3])
        : "r"(a[0]), "r"(a[1]), "r"(a[2]), "r"(a[3]), "r"(b0), "r"(b1));
}
__device__ __forceinline__ void cp16(uint32_t dst, const void* src) {
    asm volatile("cp.async.cg.shared.global [%0], [%1], 16;" :: "r"(dst), "l"(src));
}
#define CP_COMMIT() asm volatile("cp.async.commit_group;" ::: "memory")
#define CP_WAIT(n)  asm volatile("cp.async.wait_group %0;" :: "n"(n) : "memory")

// swizzled smem offset for 64B rows (4 x 16B chunks), conflict-free ldmatrix
__device__ __forceinline__ uint32_t swz_off(int row, int chunk) {
    return (uint32_t)(row * 64 + ((chunk ^ ((row >> 1) & 3)) << 4));
}

// ---------------------------------------------------------------------------
// bf16 mma_gemm: C[M,N] = A[M,K] @ B[N,K]^T, fp32 acc.
// BM=128, BN=128, BK=32, 256 threads = 8 warps (2 m x 4 n), warp tile 64x32.
// 3-stage cp.async pipeline.  Requires niter >= 2.
// EPI 1: interaction+exp -> bf16, per-block row sums -> psum.
// EPI 2: plain bf16 out.
// EPI 4: c / S[row] + bias[col] -> fp32 out.
// ---------------------------------------------------------------------------
static constexpr int MG_STAGES = 3;
static constexpr int MG_SMEM   = MG_STAGES * 16384;   // 48 KB dynamic

template <int EPI>
__global__ __launch_bounds__(256) void mma_gemm(
    const __nv_bfloat16* __restrict__ A, const __nv_bfloat16* __restrict__ B,
    void* __restrict__ Cv, int ldA, int ldB, int ldC, int niter,
    const float* __restrict__ rowv,   // EPI1: x2   | EPI4: S
    const float* __restrict__ p2,     // EPI1: p2
    const float* __restrict__ colv,   // EPI1: scale | EPI4: cvec bias
    float* __restrict__ psum)         // EPI1: per-block row sums
{
    extern __shared__ __align__(128) char dsm[];
    __shared__ float p2s[128], scs[128];
    __shared__ float bsum[4][128];

    const int tid  = threadIdx.x;
    const int lane = tid & 31, wid = tid >> 5;
    const int warp_m = wid >> 2, warp_n = wid & 3;
    const int bm = blockIdx.y * 128, bn = blockIdx.x * 128;

    if ((EPI == 1 || EPI == 4) && tid < 128) {
        if (EPI == 1) p2s[tid] = p2[bn + tid];
        scs[tid] = colv[bn + tid];
    }

    const int lrow = tid >> 2;
    const int lchk = tid & 3;
    const uint32_t su = smem_to_u32(dsm);

    auto issue = [&](int it) {
        const int slot = it % MG_STAGES;
        const int k0 = it * 32;
        const uint32_t ab = su + slot * 16384;
        const uint32_t bb = ab + 8192;
#pragma unroll
        for (int h = 0; h < 2; h++) {
            const int r = lrow + h * 64;
            cp16(ab + swz_off(r, lchk), A + (size_t)(bm + r) * ldA + k0 + lchk * 8);
            cp16(bb + swz_off(r, lchk), B + (size_t)(bn + r) * ldB + k0 + lchk * 8);
        }
        CP_COMMIT();
    };

    issue(0);
    issue(1);

    float acc[4][4][4] = {};
    const int rin = lane & 7, matid = lane >> 3;

    for (int it = 0; it < niter; it++) {
        if (it == niter - 1) CP_WAIT(0); else CP_WAIT(1);
        __syncthreads();
        if (it + MG_STAGES - 1 < niter) issue(it + MG_STAGES - 1);

        const uint32_t a_s = su + (it % MG_STAGES) * 16384;
        const uint32_t b_s = a_s + 8192;
#pragma unroll
        for (int s = 0; s < 2; s++) {
            uint32_t af[4][4], bf[2][4];
#pragma unroll
            for (int mb = 0; mb < 4; mb++) {
                const int row = warp_m * 64 + mb * 16 + (matid & 1) * 8 + rin;
                const int chk = s * 2 + (matid >> 1);
                ldsm4(af[mb][0], af[mb][1], af[mb][2], af[mb][3], a_s + swz_off(row, chk));
            }
#pragma unroll
            for (int nb2 = 0; nb2 < 2; nb2++) {
                const int row = warp_n * 32 + nb2 * 16 + (matid >> 1) * 8 + rin;
                const int chk = s * 2 + (matid & 1);
                ldsm4(bf[nb2][0], bf[nb2][1], bf[nb2][2], bf[nb2][3], b_s + swz_off(row, chk));
            }
#pragma unroll
            for (int mb = 0; mb < 4; mb++)
#pragma unroll
                for (int nb = 0; nb < 4; nb++)
                    mma16816(acc[mb][nb], af[mb],
                             bf[nb >> 1][(nb & 1) * 2], bf[nb >> 1][(nb & 1) * 2 + 1]);
        }
    }

    // ---- epilogue ----
    const int g = lane >> 2, tig = lane & 3;
    float rs[4][2];
#pragma unroll
    for (int mb = 0; mb < 4; mb++) {
        const int r0 = warp_m * 64 + mb * 16 + g;      // local rows r0, r0+8
        float xa = 0.f, xb = 0.f, inva = 0.f, invb = 0.f;
        if (EPI == 1) { xa = rowv[bm + r0]; xb = rowv[bm + r0 + 8]; }
        if (EPI == 4) { inva = 1.0f / rowv[bm + r0]; invb = 1.0f / rowv[bm + r0 + 8]; }
        if (EPI == 1) { rs[mb][0] = 0.f; rs[mb][1] = 0.f; }
#pragma unroll
        for (int nb = 0; nb < 4; nb++) {
            const int cl = warp_n * 32 + nb * 8 + 2 * tig;
            const float* c = acc[mb][nb];
            if (EPI == 1) {
                const float p0 = p2s[cl], p1 = p2s[cl + 1];
                const float s0 = scs[cl], s1 = scs[cl + 1];
                const float q0 = fmaxf(xa - 2.f * c[0] + p0, 0.f);
                const float q1 = fmaxf(xa - 2.f * c[1] + p1, 0.f);
                const float q2 = fmaxf(xb - 2.f * c[2] + p0, 0.f);
                const float q3 = fmaxf(xb - 2.f * c[3] + p1, 0.f);
                const float e0 = __expf(s0 / (sqrtf(q0) + 0.1f));
                const float e1 = __expf(s1 / (sqrtf(q1) + 0.1f));
                const float e2 = __expf(s0 / (sqrtf(q2) + 0.1f));
                const float e3 = __expf(s1 / (sqrtf(q3) + 0.1f));
                rs[mb][0] += e0 + e1;
                rs[mb][1] += e2 + e3;
                __nv_bfloat16* Cb = reinterpret_cast<__nv_bfloat16*>(Cv);
                *reinterpret_cast<__nv_bfloat162*>(Cb + (size_t)(bm + r0) * ldC + bn + cl) =
                    __floats2bfloat162_rn(e0, e1);
                *reinterpret_cast<__nv_bfloat162*>(Cb + (size_t)(bm + r0 + 8) * ldC + bn + cl) =
                    __floats2bfloat162_rn(e2, e3);
            } else if (EPI == 2) {
                __nv_bfloat16* Cb = reinterpret_cast<__nv_bfloat16*>(Cv);
                *reinterpret_cast<__nv_bfloat162*>(Cb + (size_t)(bm + r0) * ldC + bn + cl) =
                    __floats2bfloat162_rn(c[0], c[1]);
                *reinterpret_cast<__nv_bfloat162*>(Cb + (size_t)(bm + r0 + 8) * ldC + bn + cl) =
                    __floats2bfloat162_rn(c[2], c[3]);
            } else {
                const float b0 = scs[cl], b1 = scs[cl + 1];
                float* Cf = reinterpret_cast<float*>(Cv);
                *reinterpret_cast<float2*>(Cf + (size_t)(bm + r0) * ldC + bn + cl) =
                    make_float2(fmaf(c[0], inva, b0), fmaf(c[1], inva, b1));
                *reinterpret_cast<float2*>(Cf + (size_t)(bm + r0 + 8) * ldC + bn + cl) =
                    make_float2(fmaf(c[2], invb, b0), fmaf(c[3], invb, b1));
            }
        }
    }

    if (EPI == 1) {
        // deterministic per-block row sums: reduce over tig (4 lanes), then warps
#pragma unroll
        for (int mb = 0; mb < 4; mb++) {
#pragma unroll
            for (int h = 0; h < 2; h++) {
                float v = rs[mb][h];
                v += __shfl_down_sync(0xffffffffu, v, 1);
                v += __shfl_down_sync(0xffffffffu, v, 2);
                if (tig == 0)
                    bsum[warp_n][warp_m * 64 + mb * 16 + h * 8 + g] = v;
            }
        }
        __syncthreads();
        if (tid < 128) {
            const float s = bsum[0][tid] + bsum[1][tid] + bsum[2][tid] + bsum[3][tid];
            psum[(size_t)(bm + tid) * NBLK1 + blockIdx.x] = s;
        }
    }
}

// S[row] = sum of 32 per-block partials (grid 32 x 256)
__global__ void rowsum2(const float* __restrict__ psum, float* __restrict__ S) {
    const int row = blockIdx.x * 256 + threadIdx.x;
    const float4* p = reinterpret_cast<const float4*>(psum + (size_t)row * NBLK1);
    float s = 0.f;
#pragma unroll
    for (int j = 0; j < NBLK1 / 4; j++) {
        const float4 v = p[j];
        s += v.x + v.y + v.z + v.w;
    }
    S[row] = s;
}

// ---------------------------------------------------------------------------
// conversions
// ---------------------------------------------------------------------------
// fp32 -> bf16 + row sum-of-squares (1 block / row of DIM, 128 thr)
__global__ void conv_rowsq(const float* __restrict__ A, __nv_bfloat16* __restrict__ Ab,
                           float* __restrict__ out) {
    const int row = blockIdx.x;
    const int tid = threadIdx.x;
    const float4 v = reinterpret_cast<const float4*>(A + (size_t)row * DIM)[tid];
    float s = v.x * v.x + v.y * v.y + v.z * v.z + v.w * v.w;
    union { uint2 u; __nv_bfloat162 h[2]; } w;
    w.h[0] = __floats2bfloat162_rn(v.x, v.y);
    w.h[1] = __floats2bfloat162_rn(v.z, v.w);
    reinterpret_cast<uint2*>(Ab + (size_t)row * DIM)[tid] = w.u;
#pragma unroll
    for (int off = 16; off > 0; off >>= 1) s += __shfl_down_sync(0xffffffffu, s, off);
    __shared__ float ws[4];
    if ((tid & 31) == 0) ws[tid >> 5] = s;
    __syncthreads();
    if (tid == 0) out[row] = ws[0] + ws[1] + ws[2] + ws[3];
}

// plain fp32 -> bf16 convert
__global__ void conv_only(const float* __restrict__ A, __nv_bfloat16* __restrict__ Ab) {
    const int row = blockIdx.x;
    const int tid = threadIdx.x;
    const float4 v = reinterpret_cast<const float4*>(A + (size_t)row * DIM)[tid];
    union { uint2 u; __nv_bfloat162 h[2]; } w;
    w.h[0] = __floats2bfloat162_rn(v.x, v.y);
    w.h[1] = __floats2bfloat162_rn(v.z, v.w);
    reinterpret_cast<uint2*>(Ab + (size_t)row * DIM)[tid] = w.u;
}

// cvec[d] = b_o[d] + dot(w_o[d,:], b_v)
__global__ void cvec_kernel(const float* __restrict__ w_o, const float* __restrict__ b_v,
                            const float* __restrict__ b_o, float* __restrict__ cvec) {
    const int d = blockIdx.x;
    const int tid = threadIdx.x;
    float s = 0.f;
#pragma unroll
    for (int i = tid; i < DIM; i += 128) s += w_o[(size_t)d * DIM + i] * b_v[i];
#pragma unroll
    for (int off = 16; off > 0; off >>= 1) s += __shfl_down_sync(0xffffffffu, s, off);
    __shared__ float ws[4];
    if ((tid & 31) == 0) ws[tid >> 5] = s;
    __syncthreads();
    if (tid == 0) cvec[d] = b_o[d] + ws[0] + ws[1] + ws[2] + ws[3];
}

// ---------------------------------------------------------------------------
extern "C" void kernel_launch(void* const* d_in, const int* in_sizes, int n_in,
                              void* d_out, int out_size)
{
    const float* x     = (const float*)d_in[0];
    const float* pos   = (const float*)d_in[1];
    const float* scale = (const float*)d_in[2];
    const float* w_v   = (const float*)d_in[3];
    const float* b_v   = (const float*)d_in[4];
    const float* w_o   = (const float*)d_in[5];
    const float* b_o   = (const float*)d_in[6];
    float* out = (float*)d_out;

    static float* pp2 = nullptr;
    static float *px2, *pcv, *pS, *ppsum;
    static __nv_bfloat16 *pxb, *ppb, *pwvb, *pwob, *pvalb, *pw2b, *pattn;
    if (pp2 == nullptr) {
        cudaGetSymbolAddress((void**)&pp2,   g_p2);
        cudaGetSymbolAddress((void**)&px2,   g_x2);
        cudaGetSymbolAddress((void**)&pcv,   g_cvec);
        cudaGetSymbolAddress((void**)&pS,    g_S);
        cudaGetSymbolAddress((void**)&ppsum, g_psum);
        cudaGetSymbolAddress((void**)&pxb,   g_xb);
        cudaGetSymbolAddress((void**)&ppb,   g_pb);
        cudaGetSymbolAddress((void**)&pwvb,  g_wvb);
        cudaGetSymbolAddress((void**)&pwob,  g_wob);
        cudaGetSymbolAddress((void**)&pvalb, g_valb);
        cudaGetSymbolAddress((void**)&pw2b,  g_w2b);
        cudaGetSymbolAddress((void**)&pattn, g_attn);
        cudaFuncSetAttribute(mma_gemm<1>, cudaFuncAttributeMaxDynamicSharedMemorySize, MG_SMEM);
        cudaFuncSetAttribute(mma_gemm<2>, cudaFuncAttributeMaxDynamicSharedMemorySize, MG_SMEM);
        cudaFuncSetAttribute(mma_gemm<4>, cudaFuncAttributeMaxDynamicSharedMemorySize, MG_SMEM);
    }

    // converts + norms
    conv_rowsq<<<BT,    128>>>(x,   pxb, px2);
    conv_rowsq<<<NNEUR, 128>>>(pos, ppb, pp2);
    conv_only <<<DIM,   128>>>(w_v, pwvb);
    conv_only <<<DIM,   128>>>(w_o, pwob);
    cvec_kernel<<<DIM,  128>>>(w_o, b_v, b_o, pcv);

    // values = pos @ w_v^T           (4096 x 512, K=512, bf16 out)
    mma_gemm<2><<<dim3(DIM / 128, NNEUR / 128), 256, MG_SMEM>>>(
        ppb, pwvb, pvalb, DIM, DIM, DIM, DIM / 32, nullptr, nullptr, nullptr, nullptr);

    // W2^T = w_o @ values^T          (512 x 4096, K=512, bf16 out)
    mma_gemm<2><<<dim3(NNEUR / 128, DIM / 128), 256, MG_SMEM>>>(
        pwob, pvalb, pw2b, DIM, DIM, NNEUR, DIM / 32, nullptr, nullptr, nullptr, nullptr);

    // e = exp(f(x @ pos^T))          (8192 x 4096, K=512, fused epilogue -> bf16 + psum)
    mma_gemm<1><<<dim3(NNEUR / 128, BT / 128), 256, MG_SMEM>>>(
        pxb, ppb, pattn, DIM, DIM, NNEUR, DIM / 32, px2, pp2, scale, ppsum);

    // S = row sums of e
    rowsum2<<<BT / 256, 256>>>(ppsum, pS);

    // out = (e @ W2) / S + cvec      (8192 x 512, K=4096, fp32 out)
    mma_gemm<4><<<dim3(DIM / 128, BT / 128), 256, MG_SMEM>>>(
        pattn, pw2b, out, NNEUR, NNEUR, DIM, NNEUR / 32, pS, nullptr, pcv, nullptr);
}

// round 9
// speedup vs baseline: 1.5436x; 1.0651x over previous
#include <cuda_runtime.h>
#include <cuda_bf16.h>
#include <math.h>
#include <stdint.h>

#define DIM    512
#define NNEUR  4096
#define BT     8192   // B*T
#define NBLK1  (NNEUR / 128)   // 32 column-blocks in GEMM1

// ---------------- scratch (device globals; allocation-free) ----------------
__device__ float                       g_p2[NNEUR];
__device__ float                       g_x2[BT];
__device__ float                       g_cvec[DIM];
__device__ float                       g_S[BT];
__device__ __align__(16) float         g_psum[(size_t)BT * NBLK1];     // 1 MB
__device__ __align__(16) __nv_bfloat16 g_xb[BT * DIM];                 // 8 MB
__device__ __align__(16) __nv_bfloat16 g_pb[NNEUR * DIM];              // 4 MB
__device__ __align__(16) __nv_bfloat16 g_wvb[DIM * DIM];               // 0.5 MB
__device__ __align__(16) __nv_bfloat16 g_wob[DIM * DIM];               // 0.5 MB
__device__ __align__(16) __nv_bfloat16 g_valb[NNEUR * DIM];            // 4 MB  values
__device__ __align__(16) __nv_bfloat16 g_w2b[DIM * NNEUR];             // 4 MB  W2^T
__device__ __align__(16) __nv_bfloat16 g_attn[(size_t)BT * NNEUR];     // 64 MB (e = exp)

// ---------------- warp-mma helpers (base ISA: sm_80+, no 'a' suffix) -------
__device__ __forceinline__ uint32_t smem_to_u32(const void* p) {
    uint32_t a;
    asm("{ .reg .u64 t; cvta.to.shared.u64 t, %1; cvt.u32.u64 %0, t; }" : "=r"(a) : "l"(p));
    return a;
}
__device__ __forceinline__ void ldsm4(uint32_t& r0, uint32_t& r1, uint32_t& r2,
                                      uint32_t& r3, uint32_t addr) {
    asm volatile("ldmatrix.sync.aligned.m8n8.x4.shared.b16 {%0,%1,%2,%3}, [%4];"
                 : "=r"(r0), "=r"(r1), "=r"(r2), "=r"(r3) : "r"(addr));
}
__device__ __forceinline__ void mma16816(float* c, const uint32_t* a,
                                         uint32_t b0, uint32_t b1) {
    asm volatile(
        "mma.sync.aligned.m16n8k16.row.col.f32.bf16.bf16.f32 "
        "{%0,%1,%2,%3}, {%4,%5,%6,%7}, {%8,%9}, {%0,%1,%2,%3};"
        : "+f"(c[0]), "+f"(c[1]), "+f"(c[2]), "+f"(c[3])
        : "r"(a[0]), "r"(a[1]), "r"(a[2]), "r"(a[3]), "r"(b0), "r"(b1));
}
__device__ __forceinline__ void cp16(uint32_t dst, const void* src) {
    asm volatile("cp.async.cg.shared.global [%0], [%1], 16;" :: "r"(dst), "l"(src));
}
#define CP_COMMIT() asm volatile("cp.async.commit_group;" ::: "memory")
#define CP_WAIT(n)  asm volatile("cp.async.wait_group %0;" :: "n"(n) : "memory")

// swizzled smem offset for 64B rows (4 x 16B chunks), conflict-free ldmatrix
__device__ __forceinline__ uint32_t swz_off(int row, int chunk) {
    return (uint32_t)(row * 64 + ((chunk ^ ((row >> 1) & 3)) << 4));
}

// ---------------------------------------------------------------------------
// bf16 mma_gemm: C[M,N] = A[M,K] @ B[N,K]^T, fp32 acc.
// BM=128, BN=128, BK=32, 256 threads = 8 warps (2 m x 4 n), warp tile 64x32.
// 3-stage cp.async pipeline.  Requires niter >= 2.
// EPI 1: interaction+exp -> bf16, per-block row sums -> psum.
// EPI 2: plain bf16 out.
// EPI 4: c / S[row] + bias[col] -> fp32 out.
// ---------------------------------------------------------------------------
static constexpr int MG_STAGES = 3;
static constexpr int MG_SMEM   = MG_STAGES * 16384;   // 48 KB dynamic

template <int EPI>
__global__ __launch_bounds__(256) void mma_gemm(
    const __nv_bfloat16* __restrict__ A, const __nv_bfloat16* __restrict__ B,
    void* __restrict__ Cv, int ldA, int ldB, int ldC, int niter,
    const float* __restrict__ rowv,   // EPI1: x2   | EPI4: S
    const float* __restrict__ p2,     // EPI1: p2
    const float* __restrict__ colv,   // EPI1: scale | EPI4: cvec bias
    float* __restrict__ psum)         // EPI1: per-block row sums
{
    extern __shared__ __align__(128) char dsm[];
    __shared__ float p2s[128], scs[128];
    __shared__ float bsum[4][128];

    const int tid  = threadIdx.x;
    const int lane = tid & 31, wid = tid >> 5;
    const int warp_m = wid >> 2, warp_n = wid & 3;
    const int bm = blockIdx.y * 128, bn = blockIdx.x * 128;

    if ((EPI == 1 || EPI == 4) && tid < 128) {
        if (EPI == 1) p2s[tid] = p2[bn + tid];
        scs[tid] = colv[bn + tid];
    }

    const int lrow = tid >> 2;
    const int lchk = tid & 3;
    const uint32_t su = smem_to_u32(dsm);

    auto issue = [&](int it) {
        const int slot = it % MG_STAGES;
        const int k0 = it * 32;
        const uint32_t ab = su + slot * 16384;
        const uint32_t bb = ab + 8192;
#pragma unroll
        for (int h = 0; h < 2; h++) {
            const int r = lrow + h * 64;
            cp16(ab + swz_off(r, lchk), A + (size_t)(bm + r) * ldA + k0 + lchk * 8);
            cp16(bb + swz_off(r, lchk), B + (size_t)(bn + r) * ldB + k0 + lchk * 8);
        }
        CP_COMMIT();
    };

    issue(0);
    issue(1);

    float acc[4][4][4] = {};
    const int rin = lane & 7, matid = lane >> 3;

    for (int it = 0; it < niter; it++) {
        if (it == niter - 1) CP_WAIT(0); else CP_WAIT(1);
        __syncthreads();
        if (it + MG_STAGES - 1 < niter) issue(it + MG_STAGES - 1);

        const uint32_t a_s = su + (it % MG_STAGES) * 16384;
        const uint32_t b_s = a_s + 8192;
#pragma unroll
        for (int s = 0; s < 2; s++) {
            uint32_t af[4][4], bf[2][4];
#pragma unroll
            for (int mb = 0; mb < 4; mb++) {
                const int row = warp_m * 64 + mb * 16 + (matid & 1) * 8 + rin;
                const int chk = s * 2 + (matid >> 1);
                ldsm4(af[mb][0], af[mb][1], af[mb][2], af[mb][3], a_s + swz_off(row, chk));
            }
#pragma unroll
            for (int nb2 = 0; nb2 < 2; nb2++) {
                const int row = warp_n * 32 + nb2 * 16 + (matid >> 1) * 8 + rin;
                const int chk = s * 2 + (matid & 1);
                ldsm4(bf[nb2][0], bf[nb2][1], bf[nb2][2], bf[nb2][3], b_s + swz_off(row, chk));
            }
#pragma unroll
            for (int mb = 0; mb < 4; mb++)
#pragma unroll
                for (int nb = 0; nb < 4; nb++)
                    mma16816(acc[mb][nb], af[mb],
                             bf[nb >> 1][(nb & 1) * 2], bf[nb >> 1][(nb & 1) * 2 + 1]);
        }
    }

    // ---- epilogue ----
    const int g = lane >> 2, tig = lane & 3;
    float rs[4][2];
#pragma unroll
    for (int mb = 0; mb < 4; mb++) {
        const int r0 = warp_m * 64 + mb * 16 + g;      // local rows r0, r0+8
        float xa = 0.f, xb = 0.f, inva = 0.f, invb = 0.f;
        if (EPI == 1) { xa = rowv[bm + r0]; xb = rowv[bm + r0 + 8]; }
        if (EPI == 4) { inva = 1.0f / rowv[bm + r0]; invb = 1.0f / rowv[bm + r0 + 8]; }
        if (EPI == 1) { rs[mb][0] = 0.f; rs[mb][1] = 0.f; }
#pragma unroll
        for (int nb = 0; nb < 4; nb++) {
            const int cl = warp_n * 32 + nb * 8 + 2 * tig;
            const float* c = acc[mb][nb];
            if (EPI == 1) {
                const float p0 = p2s[cl], p1 = p2s[cl + 1];
                const float s0 = scs[cl], s1 = scs[cl + 1];
                const float q0 = fmaxf(xa - 2.f * c[0] + p0, 0.f);
                const float q1 = fmaxf(xa - 2.f * c[1] + p1, 0.f);
                const float q2 = fmaxf(xb - 2.f * c[2] + p0, 0.f);
                const float q3 = fmaxf(xb - 2.f * c[3] + p1, 0.f);
                const float e0 = __expf(s0 / (sqrtf(q0) + 0.1f));
                const float e1 = __expf(s1 / (sqrtf(q1) + 0.1f));
                const float e2 = __expf(s0 / (sqrtf(q2) + 0.1f));
                const float e3 = __expf(s1 / (sqrtf(q3) + 0.1f));
                rs[mb][0] += e0 + e1;
                rs[mb][1] += e2 + e3;
                __nv_bfloat16* Cb = reinterpret_cast<__nv_bfloat16*>(Cv);
                *reinterpret_cast<__nv_bfloat162*>(Cb + (size_t)(bm + r0) * ldC + bn + cl) =
                    __floats2bfloat162_rn(e0, e1);
                *reinterpret_cast<__nv_bfloat162*>(Cb + (size_t)(bm + r0 + 8) * ldC + bn + cl) =
                    __floats2bfloat162_rn(e2, e3);
            } else if (EPI == 2) {
                __nv_bfloat16* Cb = reinterpret_cast<__nv_bfloat16*>(Cv);
                *reinterpret_cast<__nv_bfloat162*>(Cb + (size_t)(bm + r0) * ldC + bn + cl) =
                    __floats2bfloat162_rn(c[0], c[1]);
                *reinterpret_cast<__nv_bfloat162*>(Cb + (size_t)(bm + r0 + 8) * ldC + bn + cl) =
                    __floats2bfloat162_rn(c[2], c[3]);
            } else {
                const float b0 = scs[cl], b1 = scs[cl + 1];
                float* Cf = reinterpret_cast<float*>(Cv);
                *reinterpret_cast<float2*>(Cf + (size_t)(bm + r0) * ldC + bn + cl) =
                    make_float2(fmaf(c[0], inva, b0), fmaf(c[1], inva, b1));
                *reinterpret_cast<float2*>(Cf + (size_t)(bm + r0 + 8) * ldC + bn + cl) =
                    make_float2(fmaf(c[2], invb, b0), fmaf(c[3], invb, b1));
            }
        }
    }

    if (EPI == 1) {
        // deterministic per-block row sums: reduce over tig (4 lanes), then warps
#pragma unroll
        for (int mb = 0; mb < 4; mb++) {
#pragma unroll
            for (int h = 0; h < 2; h++) {
                float v = rs[mb][h];
                v += __shfl_down_sync(0xffffffffu, v, 1);
                v += __shfl_down_sync(0xffffffffu, v, 2);
                if (tig == 0)
                    bsum[warp_n][warp_m * 64 + mb * 16 + h * 8 + g] = v;
            }
        }
        __syncthreads();
        if (tid < 128) {
            const float s = bsum[0][tid] + bsum[1][tid] + bsum[2][tid] + bsum[3][tid];
            psum[(size_t)(bm + tid) * NBLK1 + blockIdx.x] = s;
        }
    }
}

// S[row] = sum of 32 per-block partials (grid 32 x 256)
__global__ void rowsum2(const float* __restrict__ psum, float* __restrict__ S) {
    const int row = blockIdx.x * 256 + threadIdx.x;
    const float4* p = reinterpret_cast<const float4*>(psum + (size_t)row * NBLK1);
    float s = 0.f;
#pragma unroll
    for (int j = 0; j < NBLK1 / 4; j++) {
        const float4 v = p[j];
        s += v.x + v.y + v.z + v.w;
    }
    S[row] = s;
}

// ---------------------------------------------------------------------------
// conversions
// ---------------------------------------------------------------------------
// merged: x (rows < BT) and pos (rows >= BT): fp32 -> bf16 + row sum-of-squares
__global__ void conv_inputs(const float* __restrict__ x, const float* __restrict__ pos,
                            __nv_bfloat16* __restrict__ xb, __nv_bfloat16* __restrict__ pb,
                            float* __restrict__ x2, float* __restrict__ p2) {
    const int row = blockIdx.x;
    const int tid = threadIdx.x;
    const float* src;
    __nv_bfloat16* dst;
    float* o;
    if (row < BT) { src = x + (size_t)row * DIM; dst = xb + (size_t)row * DIM; o = x2 + row; }
    else {
        const int r = row - BT;
        src = pos + (size_t)r * DIM; dst = pb + (size_t)r * DIM; o = p2 + r;
    }
    const float4 v = reinterpret_cast<const float4*>(src)[tid];
    float s = v.x * v.x + v.y * v.y + v.z * v.z + v.w * v.w;
    union { uint2 u; __nv_bfloat162 h[2]; } w;
    w.h[0] = __floats2bfloat162_rn(v.x, v.y);
    w.h[1] = __floats2bfloat162_rn(v.z, v.w);
    reinterpret_cast<uint2*>(dst)[tid] = w.u;
#pragma unroll
    for (int off = 16; off > 0; off >>= 1) s += __shfl_down_sync(0xffffffffu, s, off);
    __shared__ float ws[4];
    if ((tid & 31) == 0) ws[tid >> 5] = s;
    __syncthreads();
    if (tid == 0) *o = ws[0] + ws[1] + ws[2] + ws[3];
}

// merged weight converts: rows < DIM -> w_v, rows >= DIM -> w_o
__global__ void conv_weights(const float* __restrict__ wv, const float* __restrict__ wo,
                             __nv_bfloat16* __restrict__ wvb, __nv_bfloat16* __restrict__ wob) {
    const int row = blockIdx.x;
    const int tid = threadIdx.x;
    const float* src = (row < DIM) ? wv + (size_t)row * DIM
                                   : wo + (size_t)(row - DIM) * DIM;
    __nv_bfloat16* dst = (row < DIM) ? wvb + (size_t)row * DIM
                                     : wob + (size_t)(row - DIM) * DIM;
    const float4 v = reinterpret_cast<const float4*>(src)[tid];
    union { uint2 u; __nv_bfloat162 h[2]; } w;
    w.h[0] = __floats2bfloat162_rn(v.x, v.y);
    w.h[1] = __floats2bfloat162_rn(v.z, v.w);
    reinterpret_cast<uint2*>(dst)[tid] = w.u;
}

// cvec[d] = b_o[d] + dot(w_o[d,:], b_v)
__global__ void cvec_kernel(const float* __restrict__ w_o, const float* __restrict__ b_v,
                            const float* __restrict__ b_o, float* __restrict__ cvec) {
    const int d = blockIdx.x;
    const int tid = threadIdx.x;
    float s = 0.f;
#pragma unroll
    for (int i = tid; i < DIM; i += 128) s += w_o[(size_t)d * DIM + i] * b_v[i];
#pragma unroll
    for (int off = 16; off > 0; off >>= 1) s += __shfl_down_sync(0xffffffffu, s, off);
    __shared__ float ws[4];
    if ((tid & 31) == 0) ws[tid >> 5] = s;
    __syncthreads();
    if (tid == 0) cvec[d] = b_o[d] + ws[0] + ws[1] + ws[2] + ws[3];
}

// ---------------------------------------------------------------------------
extern "C" void kernel_launch(void* const* d_in, const int* in_sizes, int n_in,
                              void* d_out, int out_size)
{
    const float* x     = (const float*)d_in[0];
    const float* pos   = (const float*)d_in[1];
    const float* scale = (const float*)d_in[2];
    const float* w_v   = (const float*)d_in[3];
    const float* b_v   = (const float*)d_in[4];
    const float* w_o   = (const float*)d_in[5];
    const float* b_o   = (const float*)d_in[6];
    float* out = (float*)d_out;

    static float* pp2 = nullptr;
    static float *px2, *pcv, *pS, *ppsum;
    static __nv_bfloat16 *pxb, *ppb, *pwvb, *pwob, *pvalb, *pw2b, *pattn;
    static cudaStream_t s1;
    static cudaEvent_t ev0, ev1;
    if (pp2 == nullptr) {
        cudaGetSymbolAddress((void**)&pp2,   g_p2);
        cudaGetSymbolAddress((void**)&px2,   g_x2);
        cudaGetSymbolAddress((void**)&pcv,   g_cvec);
        cudaGetSymbolAddress((void**)&pS,    g_S);
        cudaGetSymbolAddress((void**)&ppsum, g_psum);
        cudaGetSymbolAddress((void**)&pxb,   g_xb);
        cudaGetSymbolAddress((void**)&ppb,   g_pb);
        cudaGetSymbolAddress((void**)&pwvb,  g_wvb);
        cudaGetSymbolAddress((void**)&pwob,  g_wob);
        cudaGetSymbolAddress((void**)&pvalb, g_valb);
        cudaGetSymbolAddress((void**)&pw2b,  g_w2b);
        cudaGetSymbolAddress((void**)&pattn, g_attn);
        cudaFuncSetAttribute(mma_gemm<1>, cudaFuncAttributeMaxDynamicSharedMemorySize, MG_SMEM);
        cudaFuncSetAttribute(mma_gemm<2>, cudaFuncAttributeMaxDynamicSharedMemorySize, MG_SMEM);
        cudaFuncSetAttribute(mma_gemm<4>, cudaFuncAttributeMaxDynamicSharedMemorySize, MG_SMEM);
        cudaStreamCreateWithFlags(&s1, cudaStreamNonBlocking);
        cudaEventCreateWithFlags(&ev0, cudaEventDisableTiming);
        cudaEventCreateWithFlags(&ev1, cudaEventDisableTiming);
    }

    // input converts + norms (needed by both branches)
    conv_inputs<<<BT + NNEUR, 128>>>(x, pos, pxb, ppb, px2, pp2);
    cudaEventRecord(ev0, 0);

    // ---- side stream: weight chain (independent of GEMM1) ----
    cudaStreamWaitEvent(s1, ev0, 0);
    conv_weights<<<2 * DIM, 128, 0, s1>>>(w_v, w_o, pwvb, pwob);
    cvec_kernel <<<DIM,     128, 0, s1>>>(w_o, b_v, b_o, pcv);
    // values = pos @ w_v^T           (4096 x 512, K=512, bf16 out)
    mma_gemm<2><<<dim3(DIM / 128, NNEUR / 128), 256, MG_SMEM, s1>>>(
        ppb, pwvb, pvalb, DIM, DIM, DIM, DIM / 32, nullptr, nullptr, nullptr, nullptr);
    // W2^T = w_o @ values^T          (512 x 4096, K=512, bf16 out)
    mma_gemm<2><<<dim3(NNEUR / 128, DIM / 128), 256, MG_SMEM, s1>>>(
        pwob, pvalb, pw2b, DIM, DIM, NNEUR, DIM / 32, nullptr, nullptr, nullptr, nullptr);
    cudaEventRecord(ev1, s1);

    // ---- main stream: e = exp(f(x @ pos^T)) overlaps the side chain ----
    mma_gemm<1><<<dim3(NNEUR / 128, BT / 128), 256, MG_SMEM>>>(
        pxb, ppb, pattn, DIM, DIM, NNEUR, DIM / 32, px2, pp2, scale, ppsum);

    // S = row sums of e
    rowsum2<<<BT / 256, 256>>>(ppsum, pS);

    // join, then out = (e @ W2) / S + cvec   (8192 x 512, K=4096, fp32 out)
    cudaStreamWaitEvent(0, ev1, 0);
    mma_gemm<4><<<dim3(DIM / 128, BT / 128), 256, MG_SMEM>>>(
        pattn, pw2b, out, NNEUR, NNEUR, DIM, NNEUR / 32, pS, nullptr, pcv, nullptr);
}